// round 5
// baseline (speedup 1.0000x reference)
#include <cuda_runtime.h>
#include <cstdint>

#define NN 100000
#define NE 6400000
#define F_IN 128
#define HID 16

// ---------------- static device scratch ----------------
__device__ float g_deg[NN];          // weighted in-degree, then dis=rsqrt in place
__device__ int   g_cnt[NN];          // in-degree count (edges only)
__device__ int   g_base[NN];         // segment base
__device__ int   g_cur[NN];          // scatter cursor
__device__ int   g_total;            // global segment allocator
__device__ int   g_is64;             // edges dtype flag
__device__ int   g_src[NE];
__device__ int   g_dst[NE];
struct __align__(8) ES { int s; float nr; };
__device__ ES    g_es[NE];           // dst-grouped edge records
__device__ __align__(128) float g_y[NN * HID];    // gather source
__device__ __align__(128) float g_acc[NN * HID];  // aggregated output
__device__ float g_y1[NN];
__device__ float g_acc1[NN];

// ---------------- kernels ----------------

// Detect whether the edges buffer is int64 or int32.
// int64 node ids are all < 2^31 -> every high 32-bit word is zero.
// int32 data read as 64-bit pairs has "high words" = node indices, ~never all zero.
__global__ void k_detect(const void* edges) {
    if (threadIdx.x == 0 && blockIdx.x == 0) {
        const unsigned long long* e64 = (const unsigned long long*)edges;
        int all0 = 1;
        for (int i = 0; i < 64; i++)
            if ((e64[i] >> 32) != 0ull) { all0 = 0; break; }
        g_is64 = all0;
    }
}

__global__ void k_init(float* out) {
    int i = blockIdx.x * blockDim.x + threadIdx.x;
    if (i < NN) { g_deg[i] = 1.0f; g_cnt[i] = 0; }   // self-loop weight pre-seeded
    if (i == 0) { g_total = 0; out[0] = 0.0f; }
}

// index load (dtype-robust) + weighted degree + count (scalar REDs only)
__global__ void k_deg(const void* __restrict__ edges, const float* __restrict__ w) {
    int e = blockIdx.x * blockDim.x + threadIdx.x;
    if (e >= NE) return;
    int s, d;
    if (g_is64) {
        const long long* e64 = (const long long*)edges;
        s = (int)e64[e];
        d = (int)e64[NE + e];
    } else {
        const int* e32 = (const int*)edges;
        s = e32[e];
        d = e32[NE + e];
    }
    // defensive: drop malformed edges instead of issuing wild atomics
    if ((unsigned)s >= NN || (unsigned)d >= NN) { g_src[e] = -1; g_dst[e] = 0; return; }
    g_src[e] = s;
    g_dst[e] = d;
    atomicAdd(&g_deg[d], w[e]);
    atomicAdd(&g_cnt[d], 1);
}

__global__ void k_dis() {
    int i = blockIdx.x * blockDim.x + threadIdx.x;
    if (i < NN) g_deg[i] = rsqrtf(g_deg[i]);   // deg >= 1 always
}

// segment bases via warp-aggregated allocation (no global scan)
__global__ void k_base() {
    int i = blockIdx.x * blockDim.x + threadIdx.x;
    int lane = threadIdx.x & 31;
    int c = (i < NN) ? g_cnt[i] : 0;
    int sc = c;
#pragma unroll
    for (int o = 1; o < 32; o <<= 1) {
        int v = __shfl_up_sync(0xffffffffu, sc, o);
        if (lane >= o) sc += v;
    }
    int wtot = __shfl_sync(0xffffffffu, sc, 31);
    int wbase = 0;
    if (lane == 31) wbase = atomicAdd(&g_total, wtot);
    wbase = __shfl_sync(0xffffffffu, wbase, 31);
    if (i < NN) {
        int b = wbase + sc - c;
        g_base[i] = b;
        g_cur[i]  = b;
    }
}

// scatter edges into dst-grouped segments, with per-edge norm
__global__ void k_scatter(const float* __restrict__ w) {
    int e = blockIdx.x * blockDim.x + threadIdx.x;
    if (e >= NE) return;
    int s = g_src[e];
    if (s < 0) return;                 // dropped edge
    int d = g_dst[e];
    ES r;
    r.s  = s;
    r.nr = g_deg[s] * w[e] * g_deg[d];
    int pos = atomicAdd(&g_cur[d], 1);
    if (pos < NE) g_es[pos] = r;       // defensive bound
}

// layer 1 transform: y = x @ W1
__global__ void k_xform1(const float* __restrict__ x, const float* __restrict__ W) {
    __shared__ float Ws[F_IN * HID];       // 8 KB
    __shared__ float xs[16][F_IN + 4];
    int t = threadIdx.x;
    int node0 = blockIdx.x * 16;

    for (int i = t; i < F_IN * HID; i += 256) Ws[i] = W[i];
    const float* xb = x + (size_t)node0 * F_IN;
#pragma unroll
    for (int j = 0; j < 8; j++) {
        int f = t + 256 * j;
        xs[f >> 7][f & 127] = xb[f];
    }
    __syncthreads();

    int ln = t >> 4;
    int h  = t & 15;
    float acc = 0.f;
#pragma unroll
    for (int k = 0; k < F_IN; k++)
        acc = fmaf(xs[ln][k], Ws[k * HID + h], acc);
    g_y[(node0 + ln) * HID + h] = acc;
}

// mid transform: r = relu(acc + b_prev); y = r @ W
__global__ void k_xform_mid(const float* __restrict__ W, const float* __restrict__ b) {
    __shared__ float Ws[HID * HID];
    __shared__ float bs[HID];
    int t = threadIdx.x;
    if (t < HID * HID) Ws[t] = W[t];
    if (t < HID)       bs[t] = b[t];
    __syncthreads();
    int i = blockIdx.x * blockDim.x + t;
    if (i >= NN) return;

    const float4* av = (const float4*)(g_acc + (size_t)i * HID);
    float r[HID];
#pragma unroll
    for (int q = 0; q < 4; q++) {
        float4 a = av[q];
        r[q*4+0] = fmaxf(a.x + bs[q*4+0], 0.f);
        r[q*4+1] = fmaxf(a.y + bs[q*4+1], 0.f);
        r[q*4+2] = fmaxf(a.z + bs[q*4+2], 0.f);
        r[q*4+3] = fmaxf(a.w + bs[q*4+3], 0.f);
    }
    float4* yv = (float4*)(g_y + (size_t)i * HID);
#pragma unroll
    for (int q = 0; q < 4; q++) {
        float o0 = 0.f, o1 = 0.f, o2 = 0.f, o3 = 0.f;
#pragma unroll
        for (int k = 0; k < HID; k++) {
            float rk = r[k];
            o0 = fmaf(rk, Ws[k * HID + q*4+0], o0);
            o1 = fmaf(rk, Ws[k * HID + q*4+1], o1);
            o2 = fmaf(rk, Ws[k * HID + q*4+2], o2);
            o3 = fmaf(rk, Ws[k * HID + q*4+3], o3);
        }
        yv[q] = make_float4(o0, o1, o2, o3);
    }
}

// layer 4 transform: width 16 -> 1
__global__ void k_xform4(const float* __restrict__ W, const float* __restrict__ b) {
    __shared__ float Ws[HID];
    __shared__ float bs[HID];
    int t = threadIdx.x;
    if (t < HID) { Ws[t] = W[t]; bs[t] = b[t]; }
    __syncthreads();
    int i = blockIdx.x * blockDim.x + t;
    if (i >= NN) return;

    const float4* av = (const float4*)(g_acc + (size_t)i * HID);
    float s = 0.f;
#pragma unroll
    for (int q = 0; q < 4; q++) {
        float4 a = av[q];
        s = fmaf(fmaxf(a.x + bs[q*4+0], 0.f), Ws[q*4+0], s);
        s = fmaf(fmaxf(a.y + bs[q*4+1], 0.f), Ws[q*4+1], s);
        s = fmaf(fmaxf(a.z + bs[q*4+2], 0.f), Ws[q*4+2], s);
        s = fmaf(fmaxf(a.w + bs[q*4+3], 0.f), Ws[q*4+3], s);
    }
    g_y1[i] = s;
}

// hot kernel: atomic-free segment aggregation, 16 lanes per node (lane = feature)
__global__ void __launch_bounds__(256) k_agg16() {
    int node = blockIdx.x * 16 + (threadIdx.x >> 4);
    int h    = threadIdx.x & 15;
    int beg = g_base[node];
    int cnt = g_cnt[node];

    float a0 = 0.f, a1 = 0.f;
    int j = 0;
    for (; j + 2 <= cnt; j += 2) {
        ES e0 = g_es[beg + j];
        ES e1 = g_es[beg + j + 1];
        a0 = fmaf(e0.nr, g_y[e0.s * HID + h], a0);
        a1 = fmaf(e1.nr, g_y[e1.s * HID + h], a1);
    }
    if (j < cnt) {
        ES e0 = g_es[beg + j];
        a0 = fmaf(e0.nr, g_y[e0.s * HID + h], a0);
    }
    float dis = g_deg[node];
    float self = dis * dis * g_y[node * HID + h];
    g_acc[node * HID + h] = a0 + a1 + self;
}

// width-1 aggregation: one thread per node, 4-way unrolled
__global__ void __launch_bounds__(256) k_agg1() {
    int i = blockIdx.x * blockDim.x + threadIdx.x;
    if (i >= NN) return;
    int beg = g_base[i];
    int cnt = g_cnt[i];
    float a0 = 0.f, a1 = 0.f, a2 = 0.f, a3 = 0.f;
    int j = 0;
    for (; j + 4 <= cnt; j += 4) {
        ES e0 = g_es[beg + j];
        ES e1 = g_es[beg + j + 1];
        ES e2 = g_es[beg + j + 2];
        ES e3 = g_es[beg + j + 3];
        a0 = fmaf(e0.nr, g_y1[e0.s], a0);
        a1 = fmaf(e1.nr, g_y1[e1.s], a1);
        a2 = fmaf(e2.nr, g_y1[e2.s], a2);
        a3 = fmaf(e3.nr, g_y1[e3.s], a3);
    }
    for (; j < cnt; j++) {
        ES e0 = g_es[beg + j];
        a0 = fmaf(e0.nr, g_y1[e0.s], a0);
    }
    float dis = g_deg[i];
    g_acc1[i] = a0 + a1 + a2 + a3 + dis * dis * g_y1[i];
}

// final: mean over nodes of relu(acc1 + b4)
__global__ void k_mean(const float* __restrict__ b4, float* out) {
    int i = blockIdx.x * blockDim.x + threadIdx.x;
    float v = 0.f;
    if (i < NN) v = fmaxf(g_acc1[i] + b4[0], 0.f) * (1.0f / (float)NN);
#pragma unroll
    for (int o = 16; o; o >>= 1) v += __shfl_down_sync(0xffffffffu, v, o);
    __shared__ float ws[8];
    if ((threadIdx.x & 31) == 0) ws[threadIdx.x >> 5] = v;
    __syncthreads();
    if (threadIdx.x < 8) {
        float s = ws[threadIdx.x];
#pragma unroll
        for (int o = 4; o; o >>= 1) s += __shfl_down_sync(0xffu, s, o);
        if (threadIdx.x == 0) atomicAdd(out, s);
    }
}

// ---------------- launch ----------------
extern "C" void kernel_launch(void* const* d_in, const int* in_sizes, int n_in,
                              void* d_out, int out_size) {
    const float* x     = (const float*)d_in[0];
    const void*  edges = d_in[1];                 // int32 or int64 -- detected on device
    const float* w     = (const float*)d_in[2];
    const float* W1 = (const float*)d_in[3];
    const float* b1 = (const float*)d_in[4];
    const float* W2 = (const float*)d_in[5];
    const float* b2 = (const float*)d_in[6];
    const float* W3 = (const float*)d_in[7];
    const float* b3 = (const float*)d_in[8];
    const float* W4 = (const float*)d_in[9];
    const float* b4 = (const float*)d_in[10];
    float* out = (float*)d_out;

    const int TB = 256;
    const int GN = (NN + TB - 1) / TB;      // 391
    const int GE = (NE + TB - 1) / TB;      // 25000
    const int GS = NN / 16;                 // 6250 (exact)

    k_detect<<<1, 32>>>(edges);
    k_init<<<GN, TB>>>(out);
    k_deg<<<GE, TB>>>(edges, w);
    k_dis<<<GN, TB>>>();
    k_base<<<GN, TB>>>();
    k_scatter<<<GE, TB>>>(w);

    // layer 1: 128 -> 16
    k_xform1<<<GS, TB>>>(x, W1);
    k_agg16<<<GS, TB>>>();
    // layer 2
    k_xform_mid<<<GN, TB>>>(W2, b1);
    k_agg16<<<GS, TB>>>();
    // layer 3
    k_xform_mid<<<GN, TB>>>(W3, b2);
    k_agg16<<<GS, TB>>>();
    // layer 4: 16 -> 1
    k_xform4<<<GN, TB>>>(W4, b3);
    k_agg1<<<GN, TB>>>();
    // mean pool
    k_mean<<<GN, TB>>>(b4, out);
}

// round 7
// speedup vs baseline: 1.6861x; 1.6861x over previous
#include <cuda_runtime.h>
#include <cstdint>

#define NN 100000
#define NE 6400000
#define F_IN 128
#define HID 16

// ---------------- static device scratch ----------------
__device__ unsigned long long g_pack[NN];  // (count<<48) | fixed-point weight sum
__device__ float g_deg[NN];          // dis = rsqrt(deg) after k_disbase
__device__ int   g_cnt[NN];
__device__ int   g_base[NN];
__device__ int   g_cur[NN];
__device__ int   g_total;
__device__ int   g_is64;
__device__ int   g_src[NE];
__device__ int   g_dst[NE];
struct __align__(8) ES { int s; float nr; };
__device__ ES    g_es[NE];
__device__ __align__(128) float g_y[NN * HID];
__device__ __align__(128) float g_acc[NN * HID];
__device__ float g_y1[NN];
__device__ float g_acc1[NN];

#define FIXS 268435456.0f          // 2^28
#define FIXI (1.0f / 268435456.0f)

// ---------------- kernels ----------------

// init + dtype detect (int64 ids < 2^31 -> all high words zero)
__global__ void k_init(const void* edges, float* out) {
    int i = blockIdx.x * blockDim.x + threadIdx.x;
    if (i < NN) g_pack[i] = 0ull;
    if (i == 0) {
        g_total = 0; out[0] = 0.0f;
        const unsigned long long* e64 = (const unsigned long long*)edges;
        int all0 = 1;
        for (int k = 0; k < 64; k++)
            if ((e64[k] >> 32) != 0ull) { all0 = 0; break; }
        g_is64 = all0;
    }
}

// one fused 64-bit RED per edge: count + fixed-point weighted degree
__global__ void k_deg(const void* __restrict__ edges, const float* __restrict__ w) {
    int e = blockIdx.x * blockDim.x + threadIdx.x;
    if (e >= NE) return;
    int s, d;
    if (g_is64) {
        const long long* e64 = (const long long*)edges;
        s = (int)e64[e];
        d = (int)e64[NE + e];
    } else {
        const int* e32 = (const int*)edges;
        s = e32[e];
        d = e32[NE + e];
    }
    if ((unsigned)s >= NN || (unsigned)d >= NN) { g_src[e] = -1; g_dst[e] = 0; return; }
    g_src[e] = s;
    g_dst[e] = d;
    unsigned long long p = (1ull << 48) | (unsigned long long)(w[e] * FIXS + 0.5f);
    atomicAdd(&g_pack[d], p);
}

// unpack -> dis = rsqrt(1 + degsum); cnt; segment bases via warp-aggregated alloc
__global__ void k_disbase() {
    int i = blockIdx.x * blockDim.x + threadIdx.x;
    int lane = threadIdx.x & 31;
    int c = 0;
    if (i < NN) {
        unsigned long long v = g_pack[i];
        c = (int)(v >> 48);
        float deg = 1.0f + (float)(v & 0xFFFFFFFFFFFFull) * FIXI;  // self-loop +1
        g_deg[i] = rsqrtf(deg);
        g_cnt[i] = c;
    }
    int sc = c;
#pragma unroll
    for (int o = 1; o < 32; o <<= 1) {
        int v = __shfl_up_sync(0xffffffffu, sc, o);
        if (lane >= o) sc += v;
    }
    int wtot = __shfl_sync(0xffffffffu, sc, 31);
    int wbase = 0;
    if (lane == 31) wbase = atomicAdd(&g_total, wtot);
    wbase = __shfl_sync(0xffffffffu, wbase, 31);
    if (i < NN) {
        int b = wbase + sc - c;
        g_base[i] = b;
        g_cur[i]  = b;
    }
}

// scatter edges into dst-grouped segments with per-edge norm
__global__ void k_scatter(const float* __restrict__ w) {
    int e = blockIdx.x * blockDim.x + threadIdx.x;
    if (e >= NE) return;
    int s = g_src[e];
    if (s < 0) return;
    int d = g_dst[e];
    ES r;
    r.s  = s;
    r.nr = g_deg[s] * w[e] * g_deg[d];
    int pos = atomicAdd(&g_cur[d], 1);
    if (pos < NE) g_es[pos] = r;
}

// layer 1 transform: y = x @ W1
__global__ void k_xform1(const float* __restrict__ x, const float* __restrict__ W) {
    __shared__ float Ws[F_IN * HID];
    __shared__ float xs[16][F_IN + 4];
    int t = threadIdx.x;
    int node0 = blockIdx.x * 16;

    for (int i = t; i < F_IN * HID; i += 256) Ws[i] = W[i];
    const float* xb = x + (size_t)node0 * F_IN;
#pragma unroll
    for (int j = 0; j < 8; j++) {
        int f = t + 256 * j;
        xs[f >> 7][f & 127] = xb[f];
    }
    __syncthreads();

    int ln = t >> 4;
    int h  = t & 15;
    float acc = 0.f;
#pragma unroll
    for (int k = 0; k < F_IN; k++)
        acc = fmaf(xs[ln][k], Ws[k * HID + h], acc);
    g_y[(node0 + ln) * HID + h] = acc;
}

// mid transform: r = relu(acc + b_prev); y = r @ W
__global__ void k_xform_mid(const float* __restrict__ W, const float* __restrict__ b) {
    __shared__ float Ws[HID * HID];
    __shared__ float bs[HID];
    int t = threadIdx.x;
    if (t < HID * HID) Ws[t] = W[t];
    if (t < HID)       bs[t] = b[t];
    __syncthreads();
    int i = blockIdx.x * blockDim.x + t;
    if (i >= NN) return;

    const float4* av = (const float4*)(g_acc + (size_t)i * HID);
    float r[HID];
#pragma unroll
    for (int q = 0; q < 4; q++) {
        float4 a = av[q];
        r[q*4+0] = fmaxf(a.x + bs[q*4+0], 0.f);
        r[q*4+1] = fmaxf(a.y + bs[q*4+1], 0.f);
        r[q*4+2] = fmaxf(a.z + bs[q*4+2], 0.f);
        r[q*4+3] = fmaxf(a.w + bs[q*4+3], 0.f);
    }
    float4* yv = (float4*)(g_y + (size_t)i * HID);
#pragma unroll
    for (int q = 0; q < 4; q++) {
        float o0 = 0.f, o1 = 0.f, o2 = 0.f, o3 = 0.f;
#pragma unroll
        for (int k = 0; k < HID; k++) {
            float rk = r[k];
            o0 = fmaf(rk, Ws[k * HID + q*4+0], o0);
            o1 = fmaf(rk, Ws[k * HID + q*4+1], o1);
            o2 = fmaf(rk, Ws[k * HID + q*4+2], o2);
            o3 = fmaf(rk, Ws[k * HID + q*4+3], o3);
        }
        yv[q] = make_float4(o0, o1, o2, o3);
    }
}

// layer 4 transform: width 16 -> 1
__global__ void k_xform4(const float* __restrict__ W, const float* __restrict__ b) {
    __shared__ float Ws[HID];
    __shared__ float bs[HID];
    int t = threadIdx.x;
    if (t < HID) { Ws[t] = W[t]; bs[t] = b[t]; }
    __syncthreads();
    int i = blockIdx.x * blockDim.x + t;
    if (i >= NN) return;

    const float4* av = (const float4*)(g_acc + (size_t)i * HID);
    float s = 0.f;
#pragma unroll
    for (int q = 0; q < 4; q++) {
        float4 a = av[q];
        s = fmaf(fmaxf(a.x + bs[q*4+0], 0.f), Ws[q*4+0], s);
        s = fmaf(fmaxf(a.y + bs[q*4+1], 0.f), Ws[q*4+1], s);
        s = fmaf(fmaxf(a.z + bs[q*4+2], 0.f), Ws[q*4+2], s);
        s = fmaf(fmaxf(a.w + bs[q*4+3], 0.f), Ws[q*4+3], s);
    }
    g_y1[i] = s;
}

// hot kernel: warp-per-node aggregation, smem-staged edge records.
// ES loads: coalesced 32-wide (2 wf / 32 edges). y gathers: 1 wf/edge.
__global__ void __launch_bounds__(256) k_agg16() {
    __shared__ ES stage[8][32];
    int wid  = threadIdx.x >> 5;
    int lane = threadIdx.x & 31;
    int node = blockIdx.x * 8 + wid;
    if (node >= NN) return;
    int beg = g_base[node];
    int cnt = g_cnt[node];
    int h = lane & 15;
    int half = lane >> 4;          // 0: even edges, 1: odd edges

    float acc = 0.f;
    int nfull = cnt & ~31;
    for (int c0 = 0; c0 < nfull; c0 += 32) {
        stage[wid][lane] = g_es[beg + c0 + lane];
        __syncwarp();
#pragma unroll
        for (int j = 0; j < 32; j += 2) {
            ES e = stage[wid][j + half];
            acc = fmaf(e.nr, g_y[e.s * HID + h], acc);
        }
        __syncwarp();
    }
    int rem = cnt - nfull;
    if (rem) {
        if (lane < rem) stage[wid][lane] = g_es[beg + nfull + lane];
        __syncwarp();
        for (int j = 0; j < rem; j += 2) {
            int idx = j + half;
            if (idx < rem) {
                ES e = stage[wid][idx];
                acc = fmaf(e.nr, g_y[e.s * HID + h], acc);
            }
        }
        __syncwarp();
    }
    // fold odd-edge half into even-edge half
    acc += __shfl_down_sync(0xffffffffu, acc, 16);
    if (lane < 16) {
        float dis = g_deg[node];
        g_acc[node * HID + h] = acc + dis * dis * g_y[node * HID + h];
    }
}

// width-1 aggregation: warp per node, lane-parallel over edges (coalesced ES)
__global__ void __launch_bounds__(256) k_agg1() {
    int wid  = threadIdx.x >> 5;
    int lane = threadIdx.x & 31;
    int node = blockIdx.x * 8 + wid;
    if (node >= NN) return;
    int beg = g_base[node];
    int cnt = g_cnt[node];

    float acc = 0.f;
    for (int c0 = lane; c0 < cnt; c0 += 32) {
        ES e = g_es[beg + c0];
        acc = fmaf(e.nr, g_y1[e.s], acc);
    }
#pragma unroll
    for (int o = 16; o; o >>= 1) acc += __shfl_down_sync(0xffffffffu, acc, o);
    if (lane == 0) {
        float dis = g_deg[node];
        g_acc1[node] = acc + dis * dis * g_y1[node];
    }
}

// final: mean over nodes of relu(acc1 + b4)
__global__ void k_mean(const float* __restrict__ b4, float* out) {
    int i = blockIdx.x * blockDim.x + threadIdx.x;
    float v = 0.f;
    if (i < NN) v = fmaxf(g_acc1[i] + b4[0], 0.f) * (1.0f / (float)NN);
#pragma unroll
    for (int o = 16; o; o >>= 1) v += __shfl_down_sync(0xffffffffu, v, o);
    __shared__ float ws[8];
    if ((threadIdx.x & 31) == 0) ws[threadIdx.x >> 5] = v;
    __syncthreads();
    if (threadIdx.x < 8) {
        float s = ws[threadIdx.x];
#pragma unroll
        for (int o = 4; o; o >>= 1) s += __shfl_down_sync(0xffu, s, o);
        if (threadIdx.x == 0) atomicAdd(out, s);
    }
}

// ---------------- launch ----------------
extern "C" void kernel_launch(void* const* d_in, const int* in_sizes, int n_in,
                              void* d_out, int out_size) {
    const float* x     = (const float*)d_in[0];
    const void*  edges = d_in[1];
    const float* w     = (const float*)d_in[2];
    const float* W1 = (const float*)d_in[3];
    const float* b1 = (const float*)d_in[4];
    const float* W2 = (const float*)d_in[5];
    const float* b2 = (const float*)d_in[6];
    const float* W3 = (const float*)d_in[7];
    const float* b3 = (const float*)d_in[8];
    const float* W4 = (const float*)d_in[9];
    const float* b4 = (const float*)d_in[10];
    float* out = (float*)d_out;

    const int TB = 256;
    const int GN = (NN + TB - 1) / TB;       // 391
    const int GE = (NE + TB - 1) / TB;       // 25000
    const int GS = NN / 16;                  // 6250
    const int GW = (NN + 7) / 8;             // 12500 (warp-per-node kernels)

    k_init<<<GN, TB>>>(edges, out);          // 0
    k_deg<<<GE, TB>>>(edges, w);             // 1
    k_disbase<<<GN, TB>>>();                 // 2
    k_scatter<<<GE, TB>>>(w);                // 3

    k_xform1<<<GS, TB>>>(x, W1);             // 4
    k_agg16<<<GW, TB>>>();                   // 5  <- ncu capture window
    k_xform_mid<<<GN, TB>>>(W2, b1);         // 6
    k_agg16<<<GW, TB>>>();                   // 7
    k_xform_mid<<<GN, TB>>>(W3, b2);         // 8
    k_agg16<<<GW, TB>>>();                   // 9
    k_xform4<<<GN, TB>>>(W4, b3);            // 10
    k_agg1<<<GW, TB>>>();                    // 11
    k_mean<<<GN, TB>>>(b4, out);             // 12
}

// round 14
// speedup vs baseline: 1.7488x; 1.0372x over previous
#include <cuda_runtime.h>
#include <cuda_fp16.h>
#include <cstdint>

#define NN 100000
#define NE 6400000
#define F_IN 128
#define HID 16

// ---------------- static device scratch ----------------
__device__ unsigned long long g_pack[NN];  // (count<<48) | fixed-point weight sum
__device__ float g_deg[NN];          // dis = rsqrt(deg) after k_disbase
__device__ int   g_cnt[NN];
__device__ int   g_base[NN];
__device__ int   g_cur[NN];
__device__ int   g_total;
__device__ int   g_is64;
__device__ int   g_src[NE];
__device__ int   g_dst[NE];
struct __align__(8) ES { int s; float nr; };   // nr = dis[s] * w  (dis[d] hoisted)
__device__ ES    g_es[NE];
__device__ __align__(128) __half g_yh[NN * HID];   // fp16 gather table (32B/row)
__device__ __align__(128) float  g_acc[NN * HID];
__device__ float g_y1[NN];
__device__ float g_acc1[NN];

#define FIXS 268435456.0f          // 2^28
#define FIXI (1.0f / 268435456.0f)

// ---------------- kernels ----------------

// init + dtype detect (int64 ids < 2^31 -> all high words zero)
__global__ void k_init(const void* edges, float* out) {
    int i = blockIdx.x * blockDim.x + threadIdx.x;
    if (i < NN) g_pack[i] = 0ull;
    if (i == 0) {
        g_total = 0; out[0] = 0.0f;
        const unsigned long long* e64 = (const unsigned long long*)edges;
        int all0 = 1;
        for (int k = 0; k < 64; k++)
            if ((e64[k] >> 32) != 0ull) { all0 = 0; break; }
        g_is64 = all0;
    }
}

// one fused 64-bit RED per edge: count + fixed-point weighted degree
__global__ void k_deg(const void* __restrict__ edges, const float* __restrict__ w) {
    int e = blockIdx.x * blockDim.x + threadIdx.x;
    if (e >= NE) return;
    int s, d;
    if (g_is64) {
        const long long* e64 = (const long long*)edges;
        s = (int)e64[e];
        d = (int)e64[NE + e];
    } else {
        const int* e32 = (const int*)edges;
        s = e32[e];
        d = e32[NE + e];
    }
    if ((unsigned)s >= NN || (unsigned)d >= NN) { g_src[e] = -1; g_dst[e] = 0; return; }
    g_src[e] = s;
    g_dst[e] = d;
    unsigned long long p = (1ull << 48) | (unsigned long long)(w[e] * FIXS + 0.5f);
    atomicAdd(&g_pack[d], p);
}

// unpack -> dis = rsqrt(1 + degsum); cnt; segment bases via warp-aggregated alloc
__global__ void k_disbase() {
    int i = blockIdx.x * blockDim.x + threadIdx.x;
    int lane = threadIdx.x & 31;
    int c = 0;
    if (i < NN) {
        unsigned long long v = g_pack[i];
        c = (int)(v >> 48);
        float deg = 1.0f + (float)(v & 0xFFFFFFFFFFFFull) * FIXI;  // self-loop +1
        g_deg[i] = rsqrtf(deg);
        g_cnt[i] = c;
    }
    int sc = c;
#pragma unroll
    for (int o = 1; o < 32; o <<= 1) {
        int v = __shfl_up_sync(0xffffffffu, sc, o);
        if (lane >= o) sc += v;
    }
    int wtot = __shfl_sync(0xffffffffu, sc, 31);
    int wbase = 0;
    if (lane == 31) wbase = atomicAdd(&g_total, wtot);
    wbase = __shfl_sync(0xffffffffu, wbase, 31);
    if (i < NN) {
        int b = wbase + sc - c;
        g_base[i] = b;
        g_cur[i]  = b;
    }
}

// scatter edges into dst-grouped segments; nr = dis[s]*w (ONE gather per edge)
__global__ void k_scatter(const float* __restrict__ w) {
    int e = blockIdx.x * blockDim.x + threadIdx.x;
    if (e >= NE) return;
    int s = g_src[e];
    if (s < 0) return;
    int d = g_dst[e];
    ES r;
    r.s  = s;
    r.nr = g_deg[s] * w[e];
    int pos = atomicAdd(&g_cur[d], 1);
    if (pos < NE) g_es[pos] = r;
}

// layer 1 transform: y = x @ W1 (stored fp16)
__global__ void k_xform1(const float* __restrict__ x, const float* __restrict__ W) {
    __shared__ float Ws[F_IN * HID];
    __shared__ float xs[16][F_IN + 4];
    int t = threadIdx.x;
    int node0 = blockIdx.x * 16;

    for (int i = t; i < F_IN * HID; i += 256) Ws[i] = W[i];
    const float* xb = x + (size_t)node0 * F_IN;
#pragma unroll
    for (int j = 0; j < 8; j++) {
        int f = t + 256 * j;
        xs[f >> 7][f & 127] = xb[f];
    }
    __syncthreads();

    int ln = t >> 4;
    int h  = t & 15;
    float acc = 0.f;
#pragma unroll
    for (int k = 0; k < F_IN; k++)
        acc = fmaf(xs[ln][k], Ws[k * HID + h], acc);
    g_yh[(node0 + ln) * HID + h] = __float2half_rn(acc);
}

// mid transform: r = relu(acc + b_prev); y = r @ W (stored fp16)
__global__ void k_xform_mid(const float* __restrict__ W, const float* __restrict__ b) {
    __shared__ float Ws[HID * HID];
    __shared__ float bs[HID];
    int t = threadIdx.x;
    if (t < HID * HID) Ws[t] = W[t];
    if (t < HID)       bs[t] = b[t];
    __syncthreads();
    int i = blockIdx.x * blockDim.x + t;
    if (i >= NN) return;

    const float4* av = (const float4*)(g_acc + (size_t)i * HID);
    float r[HID];
#pragma unroll
    for (int q = 0; q < 4; q++) {
        float4 a = av[q];
        r[q*4+0] = fmaxf(a.x + bs[q*4+0], 0.f);
        r[q*4+1] = fmaxf(a.y + bs[q*4+1], 0.f);
        r[q*4+2] = fmaxf(a.z + bs[q*4+2], 0.f);
        r[q*4+3] = fmaxf(a.w + bs[q*4+3], 0.f);
    }
    float o[HID];
#pragma unroll
    for (int h = 0; h < HID; h++) {
        float s = 0.f;
#pragma unroll
        for (int k = 0; k < HID; k++) s = fmaf(r[k], Ws[k * HID + h], s);
        o[h] = s;
    }
    __half2 hbuf[8];
#pragma unroll
    for (int k = 0; k < 8; k++) hbuf[k] = __floats2half2_rn(o[2*k], o[2*k+1]);
    uint4* yv = (uint4*)(g_yh + (size_t)i * HID);
    yv[0] = *(uint4*)&hbuf[0];
    yv[1] = *(uint4*)&hbuf[4];
}

// layer 4 transform: width 16 -> 1
__global__ void k_xform4(const float* __restrict__ W, const float* __restrict__ b) {
    __shared__ float Ws[HID];
    __shared__ float bs[HID];
    int t = threadIdx.x;
    if (t < HID) { Ws[t] = W[t]; bs[t] = b[t]; }
    __syncthreads();
    int i = blockIdx.x * blockDim.x + t;
    if (i >= NN) return;

    const float4* av = (const float4*)(g_acc + (size_t)i * HID);
    float s = 0.f;
#pragma unroll
    for (int q = 0; q < 4; q++) {
        float4 a = av[q];
        s = fmaf(fmaxf(a.x + bs[q*4+0], 0.f), Ws[q*4+0], s);
        s = fmaf(fmaxf(a.y + bs[q*4+1], 0.f), Ws[q*4+1], s);
        s = fmaf(fmaxf(a.z + bs[q*4+2], 0.f), Ws[q*4+2], s);
        s = fmaf(fmaxf(a.w + bs[q*4+3], 0.f), Ws[q*4+3], s);
    }
    g_y1[i] = s;
}

// hot kernel: warp-per-node aggregation, smem-staged ES, fp16 y gather (1 sector/edge)
__global__ void __launch_bounds__(256) k_agg16() {
    __shared__ ES stage[8][32];
    int wid  = threadIdx.x >> 5;
    int lane = threadIdx.x & 31;
    int node = blockIdx.x * 8 + wid;
    if (node >= NN) return;
    int beg = g_base[node];
    int cnt = g_cnt[node];
    int h = lane & 15;
    int half = lane >> 4;          // 0: even edges, 1: odd edges

    float acc = 0.f;
    int nfull = cnt & ~31;
    for (int c0 = 0; c0 < nfull; c0 += 32) {
        stage[wid][lane] = g_es[beg + c0 + lane];
        __syncwarp();
#pragma unroll
        for (int j = 0; j < 32; j += 2) {
            ES e = stage[wid][j + half];
            acc = fmaf(e.nr, __half2float(g_yh[e.s * HID + h]), acc);
        }
        __syncwarp();
    }
    int rem = cnt - nfull;
    if (rem) {
        if (lane < rem) stage[wid][lane] = g_es[beg + nfull + lane];
        __syncwarp();
        for (int j = 0; j < rem; j += 2) {
            int idx = j + half;
            if (idx < rem) {
                ES e = stage[wid][idx];
                acc = fmaf(e.nr, __half2float(g_yh[e.s * HID + h]), acc);
            }
        }
        __syncwarp();
    }
    acc += __shfl_down_sync(0xffffffffu, acc, 16);
    if (lane < 16) {
        float dis = g_deg[node];                 // dis[d] hoisted out of per-edge norm
        float self = __half2float(g_yh[node * HID + h]);
        g_acc[node * HID + h] = dis * acc + dis * dis * self;
    }
}

// width-1 aggregation: warp per node, lane-parallel
__global__ void __launch_bounds__(256) k_agg1() {
    int wid  = threadIdx.x >> 5;
    int lane = threadIdx.x & 31;
    int node = blockIdx.x * 8 + wid;
    if (node >= NN) return;
    int beg = g_base[node];
    int cnt = g_cnt[node];

    float acc = 0.f;
    for (int c0 = lane; c0 < cnt; c0 += 32) {
        ES e = g_es[beg + c0];
        acc = fmaf(e.nr, g_y1[e.s], acc);
    }
#pragma unroll
    for (int o = 16; o; o >>= 1) acc += __shfl_down_sync(0xffffffffu, acc, o);
    if (lane == 0) {
        float dis = g_deg[node];
        g_acc1[node] = dis * acc + dis * dis * g_y1[node];
    }
}

// final: mean over nodes of relu(acc1 + b4)
__global__ void k_mean(const float* __restrict__ b4, float* out) {
    int i = blockIdx.x * blockDim.x + threadIdx.x;
    float v = 0.f;
    if (i < NN) v = fmaxf(g_acc1[i] + b4[0], 0.f) * (1.0f / (float)NN);
#pragma unroll
    for (int o = 16; o; o >>= 1) v += __shfl_down_sync(0xffffffffu, v, o);
    __shared__ float ws[8];
    if ((threadIdx.x & 31) == 0) ws[threadIdx.x >> 5] = v;
    __syncthreads();
    if (threadIdx.x < 8) {
        float s = ws[threadIdx.x];
#pragma unroll
        for (int o = 4; o; o >>= 1) s += __shfl_down_sync(0xffu, s, o);
        if (threadIdx.x == 0) atomicAdd(out, s);
    }
}

// ---------------- launch ----------------
extern "C" void kernel_launch(void* const* d_in, const int* in_sizes, int n_in,
                              void* d_out, int out_size) {
    const float* x     = (const float*)d_in[0];
    const void*  edges = d_in[1];
    const float* w     = (const float*)d_in[2];
    const float* W1 = (const float*)d_in[3];
    const float* b1 = (const float*)d_in[4];
    const float* W2 = (const float*)d_in[5];
    const float* b2 = (const float*)d_in[6];
    const float* W3 = (const float*)d_in[7];
    const float* b3 = (const float*)d_in[8];
    const float* W4 = (const float*)d_in[9];
    const float* b4 = (const float*)d_in[10];
    float* out = (float*)d_out;

    const int TB = 256;
    const int GN = (NN + TB - 1) / TB;       // 391
    const int GE = (NE + TB - 1) / TB;       // 25000
    const int GS = NN / 16;                  // 6250
    const int GW = (NN + 7) / 8;             // 12500

    k_init<<<GN, TB>>>(edges, out);          // 0
    k_deg<<<GE, TB>>>(edges, w);             // 1
    k_disbase<<<GN, TB>>>();                 // 2
    k_scatter<<<GE, TB>>>(w);                // 3

    k_xform1<<<GS, TB>>>(x, W1);             // 4
    k_agg16<<<GW, TB>>>();                   // 5
    k_xform_mid<<<GN, TB>>>(W2, b1);         // 6
    k_agg16<<<GW, TB>>>();                   // 7
    k_xform_mid<<<GN, TB>>>(W3, b2);         // 8
    k_agg16<<<GW, TB>>>();                   // 9
    k_xform4<<<GN, TB>>>(W4, b3);            // 10
    k_agg1<<<GW, TB>>>();                    // 11
    k_mean<<<GN, TB>>>(b4, out);             // 12
}